// round 1
// baseline (speedup 1.0000x reference)
#include <cuda_runtime.h>
#include <math.h>
#include <stdint.h>

#define MAXE 400000
#define MAXN 50000

// Scratch (device globals: the sanctioned alloc-free workaround)
__device__ float g_e2[(size_t)MAXE * 64];     // 102 MB: edge MLP output
__device__ float g_W [(size_t)MAXE * 1024];   // 1.64 GB: per-edge 32x32 matrices
__device__ float g_h0[(size_t)MAXN * 32];
__device__ float g_ha[(size_t)MAXN * 32];
__device__ float g_hb[(size_t)MAXN * 32];
__device__ float g_agg[(size_t)MAXN * 32];

// ---------------------------------------------------------------------------
// init: h0 = [x, zeros], agg = 0
// ---------------------------------------------------------------------------
__global__ void k_init(const float* __restrict__ x, int N) {
    int i = blockIdx.x * blockDim.x + threadIdx.x;
    if (i < N * 32) {
        int n = i >> 5, o = i & 31;
        g_h0[i] = (o < 16) ? x[n * 16 + o] : 0.0f;
        g_agg[i] = 0.0f;
    }
}

// ---------------------------------------------------------------------------
// edge MLP: e2 = relu(relu(ea@Wm0+bm0)@Wm1+bm1)   (one thread per edge)
// ---------------------------------------------------------------------------
__global__ __launch_bounds__(128) void k_edge_mlp(
    const float* __restrict__ ea,
    const float* __restrict__ Wm0, const float* __restrict__ bm0,
    const float* __restrict__ Wm1, const float* __restrict__ bm1, int E) {
    __shared__ float sW0[16 * 64];
    __shared__ float sW1[64 * 64];
    __shared__ float sb0[64], sb1[64];
    int tid = threadIdx.x;
    for (int i = tid; i < 16 * 64; i += 128) sW0[i] = Wm0[i];
    for (int i = tid; i < 64 * 64; i += 128) sW1[i] = Wm1[i];
    if (tid < 64) { sb0[tid] = bm0[tid]; sb1[tid] = bm1[tid]; }
    __syncthreads();

    int e = blockIdx.x * 128 + tid;
    if (e >= E) return;

    float a[16];
#pragma unroll
    for (int k4 = 0; k4 < 4; k4++) {
        float4 v = *(const float4*)(ea + (size_t)e * 16 + k4 * 4);
        a[k4 * 4 + 0] = v.x; a[k4 * 4 + 1] = v.y;
        a[k4 * 4 + 2] = v.z; a[k4 * 4 + 3] = v.w;
    }

    float h1[64];
#pragma unroll
    for (int l4 = 0; l4 < 16; l4++) {
        float s0 = sb0[l4 * 4 + 0], s1 = sb0[l4 * 4 + 1];
        float s2 = sb0[l4 * 4 + 2], s3 = sb0[l4 * 4 + 3];
#pragma unroll
        for (int k = 0; k < 16; k++) {
            float4 w = *(const float4*)&sW0[k * 64 + l4 * 4];
            float av = a[k];
            s0 += av * w.x; s1 += av * w.y; s2 += av * w.z; s3 += av * w.w;
        }
        h1[l4 * 4 + 0] = fmaxf(s0, 0.f); h1[l4 * 4 + 1] = fmaxf(s1, 0.f);
        h1[l4 * 4 + 2] = fmaxf(s2, 0.f); h1[l4 * 4 + 3] = fmaxf(s3, 0.f);
    }

    float* outp = g_e2 + (size_t)e * 64;
#pragma unroll
    for (int j4 = 0; j4 < 16; j4++) {
        float s0 = sb1[j4 * 4 + 0], s1 = sb1[j4 * 4 + 1];
        float s2 = sb1[j4 * 4 + 2], s3 = sb1[j4 * 4 + 3];
#pragma unroll
        for (int l = 0; l < 64; l++) {
            float4 w = *(const float4*)&sW1[l * 64 + j4 * 4];
            float hv = h1[l];
            s0 += hv * w.x; s1 += hv * w.y; s2 += hv * w.z; s3 += hv * w.w;
        }
        float4 o;
        o.x = fmaxf(s0, 0.f); o.y = fmaxf(s1, 0.f);
        o.z = fmaxf(s2, 0.f); o.w = fmaxf(s3, 0.f);
        *(float4*)(outp + j4 * 4) = o;
    }
}

// ---------------------------------------------------------------------------
// W GEMM: g_W[E,1024] = g_e2[E,64] @ Wm2[64,1024] + bm2
// classic 128x128 block tile, K=64, 8x8 per-thread micro-tile
// ---------------------------------------------------------------------------
__global__ __launch_bounds__(256) void k_wgemm(
    const float* __restrict__ B, const float* __restrict__ bias, int E) {
    __shared__ float sA[128][65];   // [m][k], +1 pad to dodge bank conflicts
    __shared__ float sB[64][128];   // [k][n]
    const float* __restrict__ A = g_e2;
    float* __restrict__ C = g_W;

    int bm = blockIdx.x * 128;
    int bn = blockIdx.y * 128;
    int tid = threadIdx.x;
    {
        int r0 = tid >> 4;
        int k4 = (tid & 15) << 2;
#pragma unroll
        for (int i = 0; i < 8; i++) {
            int r = r0 + i * 16;
            int rr = bm + r; if (rr >= E) rr = E - 1;
            float4 v = *(const float4*)(A + (size_t)rr * 64 + k4);
            sA[r][k4 + 0] = v.x; sA[r][k4 + 1] = v.y;
            sA[r][k4 + 2] = v.z; sA[r][k4 + 3] = v.w;
        }
        int c4 = (tid & 31) << 2;
        int rb = tid >> 5;
#pragma unroll
        for (int i = 0; i < 8; i++) {
            int r = rb + i * 8;
            *(float4*)&sB[r][c4] = *(const float4*)(B + (size_t)r * 1024 + bn + c4);
        }
    }
    __syncthreads();

    int tx = tid & 15, ty = tid >> 4;
    float acc[8][8];
#pragma unroll
    for (int i = 0; i < 8; i++)
#pragma unroll
        for (int j = 0; j < 8; j++) acc[i][j] = 0.f;

#pragma unroll 8
    for (int k = 0; k < 64; k++) {
        float a[8], b[8];
#pragma unroll
        for (int j = 0; j < 8; j++) a[j] = sA[ty * 8 + j][k];
        float4 b0 = *(const float4*)&sB[k][tx * 8];
        float4 b1 = *(const float4*)&sB[k][tx * 8 + 4];
        b[0] = b0.x; b[1] = b0.y; b[2] = b0.z; b[3] = b0.w;
        b[4] = b1.x; b[5] = b1.y; b[6] = b1.z; b[7] = b1.w;
#pragma unroll
        for (int i = 0; i < 8; i++)
#pragma unroll
            for (int j = 0; j < 8; j++) acc[i][j] += a[i] * b[j];
    }

    float bb[8];
#pragma unroll
    for (int c = 0; c < 8; c++) bb[c] = bias[bn + tx * 8 + c];
#pragma unroll
    for (int i = 0; i < 8; i++) {
        int row = bm + ty * 8 + i;
        if (row < E) {
            float4 v0 = make_float4(acc[i][0] + bb[0], acc[i][1] + bb[1],
                                    acc[i][2] + bb[2], acc[i][3] + bb[3]);
            float4 v1 = make_float4(acc[i][4] + bb[4], acc[i][5] + bb[5],
                                    acc[i][6] + bb[6], acc[i][7] + bb[7]);
            float* cp = C + (size_t)row * 1024 + bn + tx * 8;
            *(float4*)cp = v0;
            *(float4*)(cp + 4) = v1;
        }
    }
}

// ---------------------------------------------------------------------------
// message passing: agg[dst] += h[src] @ W_e     (one warp per edge)
// lane l streams float4 f = l + 32*i covering (h = l/8 + 4i, o4 = l%8)
// ---------------------------------------------------------------------------
__global__ __launch_bounds__(256) void k_msg(const int* __restrict__ ei, int selIn, int E) {
    int gw = (blockIdx.x * blockDim.x + threadIdx.x) >> 5;
    int lane = threadIdx.x & 31;
    if (gw >= E) return;
    const float* __restrict__ h = (selIn == 0) ? g_h0 : (selIn == 1) ? g_ha : g_hb;

    int2 sd = ((const int2*)ei)[gw];
    int src = sd.x, dst = sd.y;
    float hval = h[(size_t)src * 32 + lane];

    const float4* __restrict__ W4 = (const float4*)(g_W + (size_t)gw * 1024);
    float4 acc = make_float4(0.f, 0.f, 0.f, 0.f);
    int hbase = lane >> 3;
#pragma unroll
    for (int i = 0; i < 8; i++) {
        float4 w = W4[lane + 32 * i];
        float hs = __shfl_sync(0xffffffffu, hval, hbase + 4 * i);
        acc.x += hs * w.x; acc.y += hs * w.y; acc.z += hs * w.z; acc.w += hs * w.w;
    }
    // reduce over lanes sharing o4 (lane, lane^8, lane^16, lane^24)
    acc.x += __shfl_xor_sync(0xffffffffu, acc.x, 8);
    acc.x += __shfl_xor_sync(0xffffffffu, acc.x, 16);
    acc.y += __shfl_xor_sync(0xffffffffu, acc.y, 8);
    acc.y += __shfl_xor_sync(0xffffffffu, acc.y, 16);
    acc.z += __shfl_xor_sync(0xffffffffu, acc.z, 8);
    acc.z += __shfl_xor_sync(0xffffffffu, acc.z, 16);
    acc.w += __shfl_xor_sync(0xffffffffu, acc.w, 8);
    acc.w += __shfl_xor_sync(0xffffffffu, acc.w, 16);

    int c = lane >> 3;
    float v = (c == 0) ? acc.x : (c == 1) ? acc.y : (c == 2) ? acc.z : acc.w;
    atomicAdd(&g_agg[(size_t)dst * 32 + ((lane & 7) << 2) + c], v);
}

// ---------------------------------------------------------------------------
// node update: h_out = h_in @ root + bias + agg ; agg = 0   (warp per node)
// ---------------------------------------------------------------------------
__global__ __launch_bounds__(256) void k_update(
    int selIn, int selOut, const float* __restrict__ root,
    const float* __restrict__ bias, int N) {
    __shared__ float sroot[32 * 32];
    __shared__ float sb[32];
    int tid = threadIdx.x;
    for (int i = tid; i < 1024; i += 256) sroot[i] = root[i];
    if (tid < 32) sb[tid] = bias[tid];
    __syncthreads();

    int lane = tid & 31, w = tid >> 5;
    int n = blockIdx.x * 8 + w;
    if (n >= N) return;
    const float* __restrict__ hin = (selIn == 0) ? g_h0 : (selIn == 1) ? g_ha : g_hb;
    float* __restrict__ hout = (selOut == 1) ? g_ha : g_hb;

    float hv = hin[(size_t)n * 32 + lane];
    float acc = sb[lane] + g_agg[(size_t)n * 32 + lane];
    g_agg[(size_t)n * 32 + lane] = 0.0f;
#pragma unroll
    for (int k = 0; k < 32; k++)
        acc += __shfl_sync(0xffffffffu, hv, k) * sroot[k * 32 + lane];
    hout[(size_t)n * 32 + lane] = acc;
}

__global__ void k_zero(float* o, int n) {
    int i = blockIdx.x * blockDim.x + threadIdx.x;
    if (i < n) o[i] = 0.0f;
}

// ---------------------------------------------------------------------------
// readout: out = sum_n sigmoid(relu([h,h0]@Wi0+bi0)@Wi1+bi1) *
//                       (relu(h@Wj0+bj0)@Wj1+bj1)
// warp per node; final h lives in g_ha
// ---------------------------------------------------------------------------
__global__ __launch_bounds__(256) void k_readout(
    const float* __restrict__ Wi0, const float* __restrict__ bi0,
    const float* __restrict__ Wi1, const float* __restrict__ bi1,
    const float* __restrict__ Wj0, const float* __restrict__ bj0,
    const float* __restrict__ Wj1, const float* __restrict__ bj1,
    float* __restrict__ out, int N) {
    __shared__ float sW[64 * 128];
    __shared__ float sv1[128];
    __shared__ float sblock;
    int tid = threadIdx.x, lane = tid & 31, w = tid >> 5;
    int n = blockIdx.x * 8 + w;
    bool active = (n < N);

    for (int i = tid; i < 64 * 128; i += 256) sW[i] = Wi0[i];
    for (int i = tid; i < 128; i += 256) sv1[i] = Wi1[i];
    if (tid == 0) sblock = 0.f;
    __syncthreads();

    float za = 0.f, zb = 0.f;
    if (active) {
        za = g_ha[(size_t)n * 32 + lane];   // final h
        zb = g_h0[(size_t)n * 32 + lane];   // h0
    }

    // gate pre-activation
    float a0 = bi0[lane], a1 = bi0[lane + 32], a2 = bi0[lane + 64], a3 = bi0[lane + 96];
#pragma unroll
    for (int k = 0; k < 32; k++) {
        float zk = __shfl_sync(0xffffffffu, za, k);
        a0 += zk * sW[k * 128 + lane];
        a1 += zk * sW[k * 128 + lane + 32];
        a2 += zk * sW[k * 128 + lane + 64];
        a3 += zk * sW[k * 128 + lane + 96];
    }
#pragma unroll
    for (int k = 0; k < 32; k++) {
        float zk = __shfl_sync(0xffffffffu, zb, k);
        a0 += zk * sW[(k + 32) * 128 + lane];
        a1 += zk * sW[(k + 32) * 128 + lane + 32];
        a2 += zk * sW[(k + 32) * 128 + lane + 64];
        a3 += zk * sW[(k + 32) * 128 + lane + 96];
    }
    a0 = fmaxf(a0, 0.f); a1 = fmaxf(a1, 0.f); a2 = fmaxf(a2, 0.f); a3 = fmaxf(a3, 0.f);
    float gp = a0 * sv1[lane] + a1 * sv1[lane + 32] + a2 * sv1[lane + 64] + a3 * sv1[lane + 96];
#pragma unroll
    for (int s = 16; s > 0; s >>= 1) gp += __shfl_xor_sync(0xffffffffu, gp, s);
    float gate = 1.0f / (1.0f + expf(-(gp + bi1[0])));

    __syncthreads();   // done reading Wi0
    for (int i = tid; i < 32 * 128; i += 256) sW[i] = Wj0[i];
    for (int i = tid; i < 128; i += 256) sv1[i] = Wj1[i];
    __syncthreads();

    float b0 = bj0[lane], b1 = bj0[lane + 32], b2 = bj0[lane + 64], b3 = bj0[lane + 96];
#pragma unroll
    for (int k = 0; k < 32; k++) {
        float zk = __shfl_sync(0xffffffffu, za, k);
        b0 += zk * sW[k * 128 + lane];
        b1 += zk * sW[k * 128 + lane + 32];
        b2 += zk * sW[k * 128 + lane + 64];
        b3 += zk * sW[k * 128 + lane + 96];
    }
    b0 = fmaxf(b0, 0.f); b1 = fmaxf(b1, 0.f); b2 = fmaxf(b2, 0.f); b3 = fmaxf(b3, 0.f);
    float vp = b0 * sv1[lane] + b1 * sv1[lane + 32] + b2 * sv1[lane + 64] + b3 * sv1[lane + 96];
#pragma unroll
    for (int s = 16; s > 0; s >>= 1) vp += __shfl_xor_sync(0xffffffffu, vp, s);
    float val = vp + bj1[0];

    if (active && lane == 0) atomicAdd(&sblock, gate * val);
    __syncthreads();
    if (tid == 0) atomicAdd(out, sblock);
}

// ---------------------------------------------------------------------------
extern "C" void kernel_launch(void* const* d_in, const int* in_sizes, int n_in,
                              void* d_out, int out_size) {
    const float* x   = (const float*)d_in[0];
    const int*   ei  = (const int*)d_in[1];
    const float* ea  = (const float*)d_in[2];
    const float* Wm0 = (const float*)d_in[3];  const float* bm0 = (const float*)d_in[4];
    const float* Wm1 = (const float*)d_in[5];  const float* bm1 = (const float*)d_in[6];
    const float* Wm2 = (const float*)d_in[7];  const float* bm2 = (const float*)d_in[8];
    const float* root= (const float*)d_in[9];  const float* bias= (const float*)d_in[10];
    const float* Wi0 = (const float*)d_in[11]; const float* bi0 = (const float*)d_in[12];
    const float* Wi1 = (const float*)d_in[13]; const float* bi1 = (const float*)d_in[14];
    const float* Wj0 = (const float*)d_in[15]; const float* bj0 = (const float*)d_in[16];
    const float* Wj1 = (const float*)d_in[17]; const float* bj1 = (const float*)d_in[18];
    int N = in_sizes[0] / 16;
    int E = in_sizes[2] / 16;
    float* out = (float*)d_out;

    k_init<<<(N * 32 + 255) / 256, 256>>>(x, N);
    k_edge_mlp<<<(E + 127) / 128, 128>>>(ea, Wm0, bm0, Wm1, bm1, E);
    dim3 gg((E + 127) / 128, 8);
    k_wgemm<<<gg, 256>>>(Wm2, bm2, E);

    int msgBlocks = (E + 7) / 8;
    int nodeBlocks = (N + 7) / 8;
    // iter 1: h0 -> ha
    k_msg<<<msgBlocks, 256>>>(ei, 0, E);
    k_update<<<nodeBlocks, 256>>>(0, 1, root, bias, N);
    // iter 2: ha -> hb
    k_msg<<<msgBlocks, 256>>>(ei, 1, E);
    k_update<<<nodeBlocks, 256>>>(1, 2, root, bias, N);
    // iter 3: hb -> ha
    k_msg<<<msgBlocks, 256>>>(ei, 2, E);
    k_update<<<nodeBlocks, 256>>>(2, 1, root, bias, N);

    k_zero<<<1, 32>>>(out, out_size);
    k_readout<<<nodeBlocks, 256>>>(Wi0, bi0, Wi1, bi1, Wj0, bj0, Wj1, bj1, out, N);
}

// round 2
// speedup vs baseline: 2.4266x; 2.4266x over previous
#include <cuda_runtime.h>
#include <cuda_fp16.h>
#include <math.h>
#include <stdint.h>

#define MAXE 400000
#define MAXN 50000

// Scratch (device globals: the sanctioned alloc-free workaround)
__device__ float  g_e2[(size_t)MAXE * 64];     // 102 MB: edge MLP output
__device__ __half g_Wh[(size_t)MAXE * 1024];   // 819 MB: per-edge 32x32 matrices (fp16)
__device__ float  g_h0[(size_t)MAXN * 32];
__device__ float  g_ha[(size_t)MAXN * 32];
__device__ float  g_hb[(size_t)MAXN * 32];
__device__ float  g_agg[(size_t)MAXN * 32];

__device__ __forceinline__ float to_tf32(float x) {
    float r;
    asm("cvt.rna.tf32.f32 %0, %1;" : "=f"(r) : "f"(x));
    return r;
}

// ---------------------------------------------------------------------------
// init: h0 = [x, zeros], agg = 0
// ---------------------------------------------------------------------------
__global__ void k_init(const float* __restrict__ x, int N) {
    int i = blockIdx.x * blockDim.x + threadIdx.x;
    if (i < N * 32) {
        int n = i >> 5, o = i & 31;
        g_h0[i] = (o < 16) ? x[n * 16 + o] : 0.0f;
        g_agg[i] = 0.0f;
    }
}

// ---------------------------------------------------------------------------
// edge MLP: e2 = relu(relu(ea@Wm0+bm0)@Wm1+bm1)   (one thread per edge)
// ---------------------------------------------------------------------------
__global__ __launch_bounds__(128) void k_edge_mlp(
    const float* __restrict__ ea,
    const float* __restrict__ Wm0, const float* __restrict__ bm0,
    const float* __restrict__ Wm1, const float* __restrict__ bm1, int E) {
    __shared__ float sW0[16 * 64];
    __shared__ float sW1[64 * 64];
    __shared__ float sb0[64], sb1[64];
    int tid = threadIdx.x;
    for (int i = tid; i < 16 * 64; i += 128) sW0[i] = Wm0[i];
    for (int i = tid; i < 64 * 64; i += 128) sW1[i] = Wm1[i];
    if (tid < 64) { sb0[tid] = bm0[tid]; sb1[tid] = bm1[tid]; }
    __syncthreads();

    int e = blockIdx.x * 128 + tid;
    if (e >= E) return;

    float a[16];
#pragma unroll
    for (int k4 = 0; k4 < 4; k4++) {
        float4 v = *(const float4*)(ea + (size_t)e * 16 + k4 * 4);
        a[k4 * 4 + 0] = v.x; a[k4 * 4 + 1] = v.y;
        a[k4 * 4 + 2] = v.z; a[k4 * 4 + 3] = v.w;
    }

    float h1[64];
#pragma unroll
    for (int l4 = 0; l4 < 16; l4++) {
        float s0 = sb0[l4 * 4 + 0], s1 = sb0[l4 * 4 + 1];
        float s2 = sb0[l4 * 4 + 2], s3 = sb0[l4 * 4 + 3];
#pragma unroll
        for (int k = 0; k < 16; k++) {
            float4 w = *(const float4*)&sW0[k * 64 + l4 * 4];
            float av = a[k];
            s0 += av * w.x; s1 += av * w.y; s2 += av * w.z; s3 += av * w.w;
        }
        h1[l4 * 4 + 0] = fmaxf(s0, 0.f); h1[l4 * 4 + 1] = fmaxf(s1, 0.f);
        h1[l4 * 4 + 2] = fmaxf(s2, 0.f); h1[l4 * 4 + 3] = fmaxf(s3, 0.f);
    }

    float* outp = g_e2 + (size_t)e * 64;
#pragma unroll
    for (int j4 = 0; j4 < 16; j4++) {
        float s0 = sb1[j4 * 4 + 0], s1 = sb1[j4 * 4 + 1];
        float s2 = sb1[j4 * 4 + 2], s3 = sb1[j4 * 4 + 3];
#pragma unroll
        for (int l = 0; l < 64; l++) {
            float4 w = *(const float4*)&sW1[l * 64 + j4 * 4];
            float hv = h1[l];
            s0 += hv * w.x; s1 += hv * w.y; s2 += hv * w.z; s3 += hv * w.w;
        }
        float4 o;
        o.x = fmaxf(s0, 0.f); o.y = fmaxf(s1, 0.f);
        o.z = fmaxf(s2, 0.f); o.w = fmaxf(s3, 0.f);
        *(float4*)(outp + j4 * 4) = o;
    }
}

// ---------------------------------------------------------------------------
// W GEMM (tf32 tensor cores): g_Wh[E,1024] = fp16(g_e2[E,64] @ Wm2[64,1024] + bm2)
// block tile 128x128, K=64, 8 warps (4M x 2N), warp tile 32x64 via m16n8k8
// ---------------------------------------------------------------------------
#define APITCH 76
#define BPITCH 136
#define WGEMM_SMEM ((128 * APITCH + 64 * BPITCH) * 4)

__global__ __launch_bounds__(256) void k_wgemm(
    const float* __restrict__ B, const float* __restrict__ bias, int E) {
    extern __shared__ float smem[];
    float* sA = smem;                  // [128][APITCH]
    float* sB = smem + 128 * APITCH;   // [64][BPITCH]
    const float* __restrict__ A = g_e2;

    int bm = blockIdx.x * 128;
    int bn = blockIdx.y * 128;
    int tid = threadIdx.x;

    // stage A (tf32-rounded)
    {
        int r0 = tid >> 4;
        int k4 = (tid & 15) << 2;
#pragma unroll
        for (int i = 0; i < 8; i++) {
            int r = r0 + i * 16;
            int rr = bm + r; if (rr >= E) rr = E - 1;
            float4 v = *(const float4*)(A + (size_t)rr * 64 + k4);
            float4 o = make_float4(to_tf32(v.x), to_tf32(v.y), to_tf32(v.z), to_tf32(v.w));
            *(float4*)&sA[r * APITCH + k4] = o;
        }
        int c4 = (tid & 31) << 2;
        int rb = tid >> 5;
#pragma unroll
        for (int i = 0; i < 8; i++) {
            int r = rb + i * 8;
            float4 v = *(const float4*)(B + (size_t)r * 1024 + bn + c4);
            float4 o = make_float4(to_tf32(v.x), to_tf32(v.y), to_tf32(v.z), to_tf32(v.w));
            *(float4*)&sB[r * BPITCH + c4] = o;
        }
    }
    __syncthreads();

    int lane = tid & 31;
    int warp = tid >> 5;
    int wm = warp & 3;    // M strip of 32
    int wn = warp >> 2;   // N strip of 64
    int g = lane >> 2;    // groupID
    int c = lane & 3;     // threadID in group

    float acc[2][8][4];
#pragma unroll
    for (int mt = 0; mt < 2; mt++)
#pragma unroll
        for (int nt = 0; nt < 8; nt++)
#pragma unroll
            for (int q = 0; q < 4; q++) acc[mt][nt][q] = 0.f;

#pragma unroll
    for (int ks = 0; ks < 8; ks++) {
        int kb = ks * 8;
        float a_[2][4];
#pragma unroll
        for (int mt = 0; mt < 2; mt++) {
            int r0 = wm * 32 + mt * 16 + g;
            a_[mt][0] = sA[r0 * APITCH + kb + c];
            a_[mt][1] = sA[(r0 + 8) * APITCH + kb + c];
            a_[mt][2] = sA[r0 * APITCH + kb + c + 4];
            a_[mt][3] = sA[(r0 + 8) * APITCH + kb + c + 4];
        }
        float b_[8][2];
#pragma unroll
        for (int nt = 0; nt < 8; nt++) {
            int n0 = wn * 64 + nt * 8 + g;
            b_[nt][0] = sB[(kb + c) * BPITCH + n0];
            b_[nt][1] = sB[(kb + c + 4) * BPITCH + n0];
        }
#pragma unroll
        for (int mt = 0; mt < 2; mt++)
#pragma unroll
            for (int nt = 0; nt < 8; nt++) {
                asm volatile(
                    "mma.sync.aligned.m16n8k8.row.col.f32.tf32.tf32.f32 "
                    "{%0,%1,%2,%3}, {%4,%5,%6,%7}, {%8,%9}, {%0,%1,%2,%3};"
                    : "+f"(acc[mt][nt][0]), "+f"(acc[mt][nt][1]),
                      "+f"(acc[mt][nt][2]), "+f"(acc[mt][nt][3])
                    : "r"(__float_as_uint(a_[mt][0])), "r"(__float_as_uint(a_[mt][1])),
                      "r"(__float_as_uint(a_[mt][2])), "r"(__float_as_uint(a_[mt][3])),
                      "r"(__float_as_uint(b_[nt][0])), "r"(__float_as_uint(b_[nt][1])));
            }
    }

    // epilogue: add bias, write fp16
#pragma unroll
    for (int nt = 0; nt < 8; nt++) {
        int col = bn + wn * 64 + nt * 8 + 2 * c;
        float2 bb = *(const float2*)&bias[col];
#pragma unroll
        for (int mt = 0; mt < 2; mt++) {
            int row0 = bm + wm * 32 + mt * 16 + g;
            if (row0 < E) {
                __half2 v = __floats2half2_rn(acc[mt][nt][0] + bb.x, acc[mt][nt][1] + bb.y);
                *(__half2*)(g_Wh + (size_t)row0 * 1024 + col) = v;
            }
            int row1 = row0 + 8;
            if (row1 < E) {
                __half2 v = __floats2half2_rn(acc[mt][nt][2] + bb.x, acc[mt][nt][3] + bb.y);
                *(__half2*)(g_Wh + (size_t)row1 * 1024 + col) = v;
            }
        }
    }
}

// ---------------------------------------------------------------------------
// message passing: agg[dst] += h[src] @ W_e   (one warp per edge, fp16 W)
// chunk = lane + 32*i covers halves [8*chunk, 8*chunk+8): h = lane/4 + 8i,
// o in [8*(lane%4), +8)
// ---------------------------------------------------------------------------
__global__ __launch_bounds__(256) void k_msg(const int* __restrict__ ei, int selIn, int E) {
    int gw = (blockIdx.x * blockDim.x + threadIdx.x) >> 5;
    int lane = threadIdx.x & 31;
    if (gw >= E) return;
    const float* __restrict__ h = (selIn == 0) ? g_h0 : (selIn == 1) ? g_ha : g_hb;

    int2 sd = ((const int2*)ei)[gw];
    int src = sd.x, dst = sd.y;
    float hval = h[(size_t)src * 32 + lane];

    const uint4* __restrict__ W16 = (const uint4*)(g_Wh + (size_t)gw * 1024);
    float acc[8];
#pragma unroll
    for (int j = 0; j < 8; j++) acc[j] = 0.f;

#pragma unroll
    for (int i = 0; i < 4; i++) {
        uint4 w = W16[lane + 32 * i];
        float hs = __shfl_sync(0xffffffffu, hval, (lane >> 2) + 8 * i);
        const __half2* h2 = (const __half2*)&w;
#pragma unroll
        for (int j = 0; j < 4; j++) {
            float2 f = __half22float2(h2[j]);
            acc[2 * j]     += hs * f.x;
            acc[2 * j + 1] += hs * f.y;
        }
    }
    // reduce across the 8 lanes sharing lane%4 (strides 4, 8, 16)
#pragma unroll
    for (int m = 4; m <= 16; m <<= 1) {
#pragma unroll
        for (int j = 0; j < 8; j++)
            acc[j] += __shfl_xor_sync(0xffffffffu, acc[j], m);
    }
    // lane writes o = 8*(lane&3) + (lane>>2), value acc[lane>>2] (SEL chain)
    int k = lane >> 2;
    float v = acc[0];
    if (k == 1) v = acc[1];
    if (k == 2) v = acc[2];
    if (k == 3) v = acc[3];
    if (k == 4) v = acc[4];
    if (k == 5) v = acc[5];
    if (k == 6) v = acc[6];
    if (k == 7) v = acc[7];
    atomicAdd(&g_agg[(size_t)dst * 32 + ((lane & 3) << 3) + k], v);
}

// ---------------------------------------------------------------------------
// node update: h_out = h_in @ root + bias + agg ; agg = 0   (warp per node)
// ---------------------------------------------------------------------------
__global__ __launch_bounds__(256) void k_update(
    int selIn, int selOut, const float* __restrict__ root,
    const float* __restrict__ bias, int N) {
    __shared__ float sroot[32 * 32];
    __shared__ float sb[32];
    int tid = threadIdx.x;
    for (int i = tid; i < 1024; i += 256) sroot[i] = root[i];
    if (tid < 32) sb[tid] = bias[tid];
    __syncthreads();

    int lane = tid & 31, w = tid >> 5;
    int n = blockIdx.x * 8 + w;
    if (n >= N) return;
    const float* __restrict__ hin = (selIn == 0) ? g_h0 : (selIn == 1) ? g_ha : g_hb;
    float* __restrict__ hout = (selOut == 1) ? g_ha : g_hb;

    float hv = hin[(size_t)n * 32 + lane];
    float acc = sb[lane] + g_agg[(size_t)n * 32 + lane];
    g_agg[(size_t)n * 32 + lane] = 0.0f;
#pragma unroll
    for (int k = 0; k < 32; k++)
        acc += __shfl_sync(0xffffffffu, hv, k) * sroot[k * 32 + lane];
    hout[(size_t)n * 32 + lane] = acc;
}

__global__ void k_zero(float* o, int n) {
    int i = blockIdx.x * blockDim.x + threadIdx.x;
    if (i < n) o[i] = 0.0f;
}

// ---------------------------------------------------------------------------
// readout: out = sum_n sigmoid(relu([h,h0]@Wi0+bi0)@Wi1+bi1) *
//                       (relu(h@Wj0+bj0)@Wj1+bj1)
// warp per node; final h lives in g_ha
// ---------------------------------------------------------------------------
__global__ __launch_bounds__(256) void k_readout(
    const float* __restrict__ Wi0, const float* __restrict__ bi0,
    const float* __restrict__ Wi1, const float* __restrict__ bi1,
    const float* __restrict__ Wj0, const float* __restrict__ bj0,
    const float* __restrict__ Wj1, const float* __restrict__ bj1,
    float* __restrict__ out, int N) {
    __shared__ float sW[64 * 128];
    __shared__ float sv1[128];
    __shared__ float sblock;
    int tid = threadIdx.x, lane = tid & 31, w = tid >> 5;
    int n = blockIdx.x * 8 + w;
    bool active = (n < N);

    for (int i = tid; i < 64 * 128; i += 256) sW[i] = Wi0[i];
    for (int i = tid; i < 128; i += 256) sv1[i] = Wi1[i];
    if (tid == 0) sblock = 0.f;
    __syncthreads();

    float za = 0.f, zb = 0.f;
    if (active) {
        za = g_ha[(size_t)n * 32 + lane];   // final h
        zb = g_h0[(size_t)n * 32 + lane];   // h0
    }

    float a0 = bi0[lane], a1 = bi0[lane + 32], a2 = bi0[lane + 64], a3 = bi0[lane + 96];
#pragma unroll
    for (int k = 0; k < 32; k++) {
        float zk = __shfl_sync(0xffffffffu, za, k);
        a0 += zk * sW[k * 128 + lane];
        a1 += zk * sW[k * 128 + lane + 32];
        a2 += zk * sW[k * 128 + lane + 64];
        a3 += zk * sW[k * 128 + lane + 96];
    }
#pragma unroll
    for (int k = 0; k < 32; k++) {
        float zk = __shfl_sync(0xffffffffu, zb, k);
        a0 += zk * sW[(k + 32) * 128 + lane];
        a1 += zk * sW[(k + 32) * 128 + lane + 32];
        a2 += zk * sW[(k + 32) * 128 + lane + 64];
        a3 += zk * sW[(k + 32) * 128 + lane + 96];
    }
    a0 = fmaxf(a0, 0.f); a1 = fmaxf(a1, 0.f); a2 = fmaxf(a2, 0.f); a3 = fmaxf(a3, 0.f);
    float gp = a0 * sv1[lane] + a1 * sv1[lane + 32] + a2 * sv1[lane + 64] + a3 * sv1[lane + 96];
#pragma unroll
    for (int s = 16; s > 0; s >>= 1) gp += __shfl_xor_sync(0xffffffffu, gp, s);
    float gate = 1.0f / (1.0f + expf(-(gp + bi1[0])));

    __syncthreads();   // done reading Wi0
    for (int i = tid; i < 32 * 128; i += 256) sW[i] = Wj0[i];
    for (int i = tid; i < 128; i += 256) sv1[i] = Wj1[i];
    __syncthreads();

    float b0 = bj0[lane], b1 = bj0[lane + 32], b2 = bj0[lane + 64], b3 = bj0[lane + 96];
#pragma unroll
    for (int k = 0; k < 32; k++) {
        float zk = __shfl_sync(0xffffffffu, za, k);
        b0 += zk * sW[k * 128 + lane];
        b1 += zk * sW[k * 128 + lane + 32];
        b2 += zk * sW[k * 128 + lane + 64];
        b3 += zk * sW[k * 128 + lane + 96];
    }
    b0 = fmaxf(b0, 0.f); b1 = fmaxf(b1, 0.f); b2 = fmaxf(b2, 0.f); b3 = fmaxf(b3, 0.f);
    float vp = b0 * sv1[lane] + b1 * sv1[lane + 32] + b2 * sv1[lane + 64] + b3 * sv1[lane + 96];
#pragma unroll
    for (int s = 16; s > 0; s >>= 1) vp += __shfl_xor_sync(0xffffffffu, vp, s);
    float val = vp + bj1[0];

    if (active && lane == 0) atomicAdd(&sblock, gate * val);
    __syncthreads();
    if (tid == 0) atomicAdd(out, sblock);
}

// ---------------------------------------------------------------------------
extern "C" void kernel_launch(void* const* d_in, const int* in_sizes, int n_in,
                              void* d_out, int out_size) {
    const float* x   = (const float*)d_in[0];
    const int*   ei  = (const int*)d_in[1];
    const float* ea  = (const float*)d_in[2];
    const float* Wm0 = (const float*)d_in[3];  const float* bm0 = (const float*)d_in[4];
    const float* Wm1 = (const float*)d_in[5];  const float* bm1 = (const float*)d_in[6];
    const float* Wm2 = (const float*)d_in[7];  const float* bm2 = (const float*)d_in[8];
    const float* root= (const float*)d_in[9];  const float* bias= (const float*)d_in[10];
    const float* Wi0 = (const float*)d_in[11]; const float* bi0 = (const float*)d_in[12];
    const float* Wi1 = (const float*)d_in[13]; const float* bi1 = (const float*)d_in[14];
    const float* Wj0 = (const float*)d_in[15]; const float* bj0 = (const float*)d_in[16];
    const float* Wj1 = (const float*)d_in[17]; const float* bj1 = (const float*)d_in[18];
    int N = in_sizes[0] / 16;
    int E = in_sizes[2] / 16;
    float* out = (float*)d_out;

    k_init<<<(N * 32 + 255) / 256, 256>>>(x, N);
    k_edge_mlp<<<(E + 127) / 128, 128>>>(ea, Wm0, bm0, Wm1, bm1, E);

    cudaFuncSetAttribute(k_wgemm, cudaFuncAttributeMaxDynamicSharedMemorySize, WGEMM_SMEM);
    dim3 gg((E + 127) / 128, 8);
    k_wgemm<<<gg, 256, WGEMM_SMEM>>>(Wm2, bm2, E);

    int msgBlocks = (E + 7) / 8;
    int nodeBlocks = (N + 7) / 8;
    // iter 1: h0 -> ha
    k_msg<<<msgBlocks, 256>>>(ei, 0, E);
    k_update<<<nodeBlocks, 256>>>(0, 1, root, bias, N);
    // iter 2: ha -> hb
    k_msg<<<msgBlocks, 256>>>(ei, 1, E);
    k_update<<<nodeBlocks, 256>>>(1, 2, root, bias, N);
    // iter 3: hb -> ha
    k_msg<<<msgBlocks, 256>>>(ei, 2, E);
    k_update<<<nodeBlocks, 256>>>(2, 1, root, bias, N);

    k_zero<<<1, 32>>>(out, out_size);
    k_readout<<<nodeBlocks, 256>>>(Wi0, bi0, Wi1, bi1, Wj0, bj0, Wj1, bj1, out, N);
}

// round 3
// speedup vs baseline: 2.4303x; 1.0015x over previous
#include <cuda_runtime.h>
#include <cuda_fp16.h>
#include <math.h>
#include <stdint.h>

#define MAXE 400000
#define MAXN 50000

// Scratch (device globals: the sanctioned alloc-free workaround)
__device__ float  g_e2[(size_t)MAXE * 64];     // 102 MB: edge MLP output
__device__ __half g_Wh[(size_t)MAXE * 1024];   // 819 MB: per-edge 32x32 matrices (fp16)
__device__ float  g_h0[(size_t)MAXN * 32];
__device__ float  g_ha[(size_t)MAXN * 32];
__device__ float  g_hb[(size_t)MAXN * 32];
__device__ float  g_agg[(size_t)MAXN * 32];

__device__ __forceinline__ float to_tf32(float x) {
    float r;
    asm("cvt.rna.tf32.f32 %0, %1;" : "=f"(r) : "f"(x));
    return r;
}

// ---------------------------------------------------------------------------
// init: h0 = [x, zeros], agg = 0
// ---------------------------------------------------------------------------
__global__ void k_init(const float* __restrict__ x, int N) {
    int i = blockIdx.x * blockDim.x + threadIdx.x;
    if (i < N * 32) {
        int n = i >> 5, o = i & 31;
        g_h0[i] = (o < 16) ? x[n * 16 + o] : 0.0f;
        g_agg[i] = 0.0f;
    }
}

// ---------------------------------------------------------------------------
// edge MLP: e2 = relu(relu(ea@Wm0+bm0)@Wm1+bm1)   (one thread per edge)
// ---------------------------------------------------------------------------
__global__ __launch_bounds__(128) void k_edge_mlp(
    const float* __restrict__ ea,
    const float* __restrict__ Wm0, const float* __restrict__ bm0,
    const float* __restrict__ Wm1, const float* __restrict__ bm1, int E) {
    __shared__ float sW0[16 * 64];
    __shared__ float sW1[64 * 64];
    __shared__ float sb0[64], sb1[64];
    int tid = threadIdx.x;
    for (int i = tid; i < 16 * 64; i += 128) sW0[i] = Wm0[i];
    for (int i = tid; i < 64 * 64; i += 128) sW1[i] = Wm1[i];
    if (tid < 64) { sb0[tid] = bm0[tid]; sb1[tid] = bm1[tid]; }
    __syncthreads();

    int e = blockIdx.x * 128 + tid;
    if (e >= E) return;

    float a[16];
#pragma unroll
    for (int k4 = 0; k4 < 4; k4++) {
        float4 v = *(const float4*)(ea + (size_t)e * 16 + k4 * 4);
        a[k4 * 4 + 0] = v.x; a[k4 * 4 + 1] = v.y;
        a[k4 * 4 + 2] = v.z; a[k4 * 4 + 3] = v.w;
    }

    float h1[64];
#pragma unroll
    for (int l4 = 0; l4 < 16; l4++) {
        float s0 = sb0[l4 * 4 + 0], s1 = sb0[l4 * 4 + 1];
        float s2 = sb0[l4 * 4 + 2], s3 = sb0[l4 * 4 + 3];
#pragma unroll
        for (int k = 0; k < 16; k++) {
            float4 w = *(const float4*)&sW0[k * 64 + l4 * 4];
            float av = a[k];
            s0 += av * w.x; s1 += av * w.y; s2 += av * w.z; s3 += av * w.w;
        }
        h1[l4 * 4 + 0] = fmaxf(s0, 0.f); h1[l4 * 4 + 1] = fmaxf(s1, 0.f);
        h1[l4 * 4 + 2] = fmaxf(s2, 0.f); h1[l4 * 4 + 3] = fmaxf(s3, 0.f);
    }

    float* outp = g_e2 + (size_t)e * 64;
#pragma unroll
    for (int j4 = 0; j4 < 16; j4++) {
        float s0 = sb1[j4 * 4 + 0], s1 = sb1[j4 * 4 + 1];
        float s2 = sb1[j4 * 4 + 2], s3 = sb1[j4 * 4 + 3];
#pragma unroll
        for (int l = 0; l < 64; l++) {
            float4 w = *(const float4*)&sW1[l * 64 + j4 * 4];
            float hv = h1[l];
            s0 += hv * w.x; s1 += hv * w.y; s2 += hv * w.z; s3 += hv * w.w;
        }
        float4 o;
        o.x = fmaxf(s0, 0.f); o.y = fmaxf(s1, 0.f);
        o.z = fmaxf(s2, 0.f); o.w = fmaxf(s3, 0.f);
        *(float4*)(outp + j4 * 4) = o;
    }
}

// ---------------------------------------------------------------------------
// W GEMM (tf32 tensor cores): g_Wh[E,1024] = fp16(g_e2[E,64] @ Wm2[64,1024] + bm2)
// block tile 128x128, K=64, 8 warps (4M x 2N), warp tile 32x64 via m16n8k8
// ---------------------------------------------------------------------------
#define APITCH 76
#define BPITCH 136
#define WGEMM_SMEM ((128 * APITCH + 64 * BPITCH) * 4)

__global__ __launch_bounds__(256) void k_wgemm(
    const float* __restrict__ B, const float* __restrict__ bias, int E) {
    extern __shared__ float smem[];
    float* sA = smem;                  // [128][APITCH]
    float* sB = smem + 128 * APITCH;   // [64][BPITCH]
    const float* __restrict__ A = g_e2;

    int bm = blockIdx.x * 128;
    int bn = blockIdx.y * 128;
    int tid = threadIdx.x;

    // stage A (tf32-rounded)
    {
        int r0 = tid >> 4;
        int k4 = (tid & 15) << 2;
#pragma unroll
        for (int i = 0; i < 8; i++) {
            int r = r0 + i * 16;
            int rr = bm + r; if (rr >= E) rr = E - 1;
            float4 v = *(const float4*)(A + (size_t)rr * 64 + k4);
            float4 o = make_float4(to_tf32(v.x), to_tf32(v.y), to_tf32(v.z), to_tf32(v.w));
            *(float4*)&sA[r * APITCH + k4] = o;
        }
        int c4 = (tid & 31) << 2;
        int rb = tid >> 5;
#pragma unroll
        for (int i = 0; i < 8; i++) {
            int r = rb + i * 8;
            float4 v = *(const float4*)(B + (size_t)r * 1024 + bn + c4);
            float4 o = make_float4(to_tf32(v.x), to_tf32(v.y), to_tf32(v.z), to_tf32(v.w));
            *(float4*)&sB[r * BPITCH + c4] = o;
        }
    }
    __syncthreads();

    int lane = tid & 31;
    int warp = tid >> 5;
    int wm = warp & 3;    // M strip of 32
    int wn = warp >> 2;   // N strip of 64
    int g = lane >> 2;    // groupID
    int c = lane & 3;     // threadID in group

    float acc[2][8][4];
#pragma unroll
    for (int mt = 0; mt < 2; mt++)
#pragma unroll
        for (int nt = 0; nt < 8; nt++)
#pragma unroll
            for (int q = 0; q < 4; q++) acc[mt][nt][q] = 0.f;

#pragma unroll
    for (int ks = 0; ks < 8; ks++) {
        int kb = ks * 8;
        float a_[2][4];
#pragma unroll
        for (int mt = 0; mt < 2; mt++) {
            int r0 = wm * 32 + mt * 16 + g;
            a_[mt][0] = sA[r0 * APITCH + kb + c];
            a_[mt][1] = sA[(r0 + 8) * APITCH + kb + c];
            a_[mt][2] = sA[r0 * APITCH + kb + c + 4];
            a_[mt][3] = sA[(r0 + 8) * APITCH + kb + c + 4];
        }
        float b_[8][2];
#pragma unroll
        for (int nt = 0; nt < 8; nt++) {
            int n0 = wn * 64 + nt * 8 + g;
            b_[nt][0] = sB[(kb + c) * BPITCH + n0];
            b_[nt][1] = sB[(kb + c + 4) * BPITCH + n0];
        }
#pragma unroll
        for (int mt = 0; mt < 2; mt++)
#pragma unroll
            for (int nt = 0; nt < 8; nt++) {
                asm volatile(
                    "mma.sync.aligned.m16n8k8.row.col.f32.tf32.tf32.f32 "
                    "{%0,%1,%2,%3}, {%4,%5,%6,%7}, {%8,%9}, {%0,%1,%2,%3};"
                    : "+f"(acc[mt][nt][0]), "+f"(acc[mt][nt][1]),
                      "+f"(acc[mt][nt][2]), "+f"(acc[mt][nt][3])
                    : "r"(__float_as_uint(a_[mt][0])), "r"(__float_as_uint(a_[mt][1])),
                      "r"(__float_as_uint(a_[mt][2])), "r"(__float_as_uint(a_[mt][3])),
                      "r"(__float_as_uint(b_[nt][0])), "r"(__float_as_uint(b_[nt][1])));
            }
    }

    // epilogue: add bias, write fp16
#pragma unroll
    for (int nt = 0; nt < 8; nt++) {
        int col = bn + wn * 64 + nt * 8 + 2 * c;
        float2 bb = *(const float2*)&bias[col];
#pragma unroll
        for (int mt = 0; mt < 2; mt++) {
            int row0 = bm + wm * 32 + mt * 16 + g;
            if (row0 < E) {
                __half2 v = __floats2half2_rn(acc[mt][nt][0] + bb.x, acc[mt][nt][1] + bb.y);
                *(__half2*)(g_Wh + (size_t)row0 * 1024 + col) = v;
            }
            int row1 = row0 + 8;
            if (row1 < E) {
                __half2 v = __floats2half2_rn(acc[mt][nt][2] + bb.x, acc[mt][nt][3] + bb.y);
                *(__half2*)(g_Wh + (size_t)row1 * 1024 + col) = v;
            }
        }
    }
}

// ---------------------------------------------------------------------------
// message passing: agg[dst] += h[src] @ W_e   (one warp per edge, fp16 W)
// chunk = lane + 32*i covers halves [8*chunk, 8*chunk+8): h = lane/4 + 8i,
// o in [8*(lane%4), +8)
// ---------------------------------------------------------------------------
__global__ __launch_bounds__(256) void k_msg(const int* __restrict__ ei, int selIn, int E) {
    int gw = (blockIdx.x * blockDim.x + threadIdx.x) >> 5;
    int lane = threadIdx.x & 31;
    if (gw >= E) return;
    const float* __restrict__ h = (selIn == 0) ? g_h0 : (selIn == 1) ? g_ha : g_hb;

    int2 sd = ((const int2*)ei)[gw];
    int src = sd.x, dst = sd.y;
    float hval = h[(size_t)src * 32 + lane];

    const uint4* __restrict__ W16 = (const uint4*)(g_Wh + (size_t)gw * 1024);
    float acc[8];
#pragma unroll
    for (int j = 0; j < 8; j++) acc[j] = 0.f;

#pragma unroll
    for (int i = 0; i < 4; i++) {
        uint4 w = W16[lane + 32 * i];
        float hs = __shfl_sync(0xffffffffu, hval, (lane >> 2) + 8 * i);
        const __half2* h2 = (const __half2*)&w;
#pragma unroll
        for (int j = 0; j < 4; j++) {
            float2 f = __half22float2(h2[j]);
            acc[2 * j]     += hs * f.x;
            acc[2 * j + 1] += hs * f.y;
        }
    }
    // reduce across the 8 lanes sharing lane%4 (strides 4, 8, 16)
#pragma unroll
    for (int m = 4; m <= 16; m <<= 1) {
#pragma unroll
        for (int j = 0; j < 8; j++)
            acc[j] += __shfl_xor_sync(0xffffffffu, acc[j], m);
    }
    // lane writes o = 8*(lane&3) + (lane>>2), value acc[lane>>2] (SEL chain)
    int k = lane >> 2;
    float v = acc[0];
    if (k == 1) v = acc[1];
    if (k == 2) v = acc[2];
    if (k == 3) v = acc[3];
    if (k == 4) v = acc[4];
    if (k == 5) v = acc[5];
    if (k == 6) v = acc[6];
    if (k == 7) v = acc[7];
    atomicAdd(&g_agg[(size_t)dst * 32 + ((lane & 3) << 3) + k], v);
}

// ---------------------------------------------------------------------------
// node update: h_out = h_in @ root + bias + agg ; agg = 0   (warp per node)
// ---------------------------------------------------------------------------
__global__ __launch_bounds__(256) void k_update(
    int selIn, int selOut, const float* __restrict__ root,
    const float* __restrict__ bias, int N) {
    __shared__ float sroot[32 * 32];
    __shared__ float sb[32];
    int tid = threadIdx.x;
    for (int i = tid; i < 1024; i += 256) sroot[i] = root[i];
    if (tid < 32) sb[tid] = bias[tid];
    __syncthreads();

    int lane = tid & 31, w = tid >> 5;
    int n = blockIdx.x * 8 + w;
    if (n >= N) return;
    const float* __restrict__ hin = (selIn == 0) ? g_h0 : (selIn == 1) ? g_ha : g_hb;
    float* __restrict__ hout = (selOut == 1) ? g_ha : g_hb;

    float hv = hin[(size_t)n * 32 + lane];
    float acc = sb[lane] + g_agg[(size_t)n * 32 + lane];
    g_agg[(size_t)n * 32 + lane] = 0.0f;
#pragma unroll
    for (int k = 0; k < 32; k++)
        acc += __shfl_sync(0xffffffffu, hv, k) * sroot[k * 32 + lane];
    hout[(size_t)n * 32 + lane] = acc;
}

__global__ void k_zero(float* o, int n) {
    int i = blockIdx.x * blockDim.x + threadIdx.x;
    if (i < n) o[i] = 0.0f;
}

// ---------------------------------------------------------------------------
// readout: out = sum_n sigmoid(relu([h,h0]@Wi0+bi0)@Wi1+bi1) *
//                       (relu(h@Wj0+bj0)@Wj1+bj1)
// warp per node; final h lives in g_ha
// ---------------------------------------------------------------------------
__global__ __launch_bounds__(256) void k_readout(
    const float* __restrict__ Wi0, const float* __restrict__ bi0,
    const float* __restrict__ Wi1, const float* __restrict__ bi1,
    const float* __restrict__ Wj0, const float* __restrict__ bj0,
    const float* __restrict__ Wj1, const float* __restrict__ bj1,
    float* __restrict__ out, int N) {
    __shared__ float sW[64 * 128];
    __shared__ float sv1[128];
    __shared__ float sblock;
    int tid = threadIdx.x, lane = tid & 31, w = tid >> 5;
    int n = blockIdx.x * 8 + w;
    bool active = (n < N);

    for (int i = tid; i < 64 * 128; i += 256) sW[i] = Wi0[i];
    for (int i = tid; i < 128; i += 256) sv1[i] = Wi1[i];
    if (tid == 0) sblock = 0.f;
    __syncthreads();

    float za = 0.f, zb = 0.f;
    if (active) {
        za = g_ha[(size_t)n * 32 + lane];   // final h
        zb = g_h0[(size_t)n * 32 + lane];   // h0
    }

    float a0 = bi0[lane], a1 = bi0[lane + 32], a2 = bi0[lane + 64], a3 = bi0[lane + 96];
#pragma unroll
    for (int k = 0; k < 32; k++) {
        float zk = __shfl_sync(0xffffffffu, za, k);
        a0 += zk * sW[k * 128 + lane];
        a1 += zk * sW[k * 128 + lane + 32];
        a2 += zk * sW[k * 128 + lane + 64];
        a3 += zk * sW[k * 128 + lane + 96];
    }
#pragma unroll
    for (int k = 0; k < 32; k++) {
        float zk = __shfl_sync(0xffffffffu, zb, k);
        a0 += zk * sW[(k + 32) * 128 + lane];
        a1 += zk * sW[(k + 32) * 128 + lane + 32];
        a2 += zk * sW[(k + 32) * 128 + lane + 64];
        a3 += zk * sW[(k + 32) * 128 + lane + 96];
    }
    a0 = fmaxf(a0, 0.f); a1 = fmaxf(a1, 0.f); a2 = fmaxf(a2, 0.f); a3 = fmaxf(a3, 0.f);
    float gp = a0 * sv1[lane] + a1 * sv1[lane + 32] + a2 * sv1[lane + 64] + a3 * sv1[lane + 96];
#pragma unroll
    for (int s = 16; s > 0; s >>= 1) gp += __shfl_xor_sync(0xffffffffu, gp, s);
    float gate = 1.0f / (1.0f + expf(-(gp + bi1[0])));

    __syncthreads();   // done reading Wi0
    for (int i = tid; i < 32 * 128; i += 256) sW[i] = Wj0[i];
    for (int i = tid; i < 128; i += 256) sv1[i] = Wj1[i];
    __syncthreads();

    float b0 = bj0[lane], b1 = bj0[lane + 32], b2 = bj0[lane + 64], b3 = bj0[lane + 96];
#pragma unroll
    for (int k = 0; k < 32; k++) {
        float zk = __shfl_sync(0xffffffffu, za, k);
        b0 += zk * sW[k * 128 + lane];
        b1 += zk * sW[k * 128 + lane + 32];
        b2 += zk * sW[k * 128 + lane + 64];
        b3 += zk * sW[k * 128 + lane + 96];
    }
    b0 = fmaxf(b0, 0.f); b1 = fmaxf(b1, 0.f); b2 = fmaxf(b2, 0.f); b3 = fmaxf(b3, 0.f);
    float vp = b0 * sv1[lane] + b1 * sv1[lane + 32] + b2 * sv1[lane + 64] + b3 * sv1[lane + 96];
#pragma unroll
    for (int s = 16; s > 0; s >>= 1) vp += __shfl_xor_sync(0xffffffffu, vp, s);
    float val = vp + bj1[0];

    if (active && lane == 0) atomicAdd(&sblock, gate * val);
    __syncthreads();
    if (tid == 0) atomicAdd(out, sblock);
}

// ---------------------------------------------------------------------------
extern "C" void kernel_launch(void* const* d_in, const int* in_sizes, int n_in,
                              void* d_out, int out_size) {
    const float* x   = (const float*)d_in[0];
    const int*   ei  = (const int*)d_in[1];
    const float* ea  = (const float*)d_in[2];
    const float* Wm0 = (const float*)d_in[3];  const float* bm0 = (const float*)d_in[4];
    const float* Wm1 = (const float*)d_in[5];  const float* bm1 = (const float*)d_in[6];
    const float* Wm2 = (const float*)d_in[7];  const float* bm2 = (const float*)d_in[8];
    const float* root= (const float*)d_in[9];  const float* bias= (const float*)d_in[10];
    const float* Wi0 = (const float*)d_in[11]; const float* bi0 = (const float*)d_in[12];
    const float* Wi1 = (const float*)d_in[13]; const float* bi1 = (const float*)d_in[14];
    const float* Wj0 = (const float*)d_in[15]; const float* bj0 = (const float*)d_in[16];
    const float* Wj1 = (const float*)d_in[17]; const float* bj1 = (const float*)d_in[18];
    int N = in_sizes[0] / 16;
    int E = in_sizes[2] / 16;
    float* out = (float*)d_out;

    k_init<<<(N * 32 + 255) / 256, 256>>>(x, N);
    k_edge_mlp<<<(E + 127) / 128, 128>>>(ea, Wm0, bm0, Wm1, bm1, E);

    cudaFuncSetAttribute(k_wgemm, cudaFuncAttributeMaxDynamicSharedMemorySize, WGEMM_SMEM);
    dim3 gg((E + 127) / 128, 8);
    k_wgemm<<<gg, 256, WGEMM_SMEM>>>(Wm2, bm2, E);

    int msgBlocks = (E + 7) / 8;
    int nodeBlocks = (N + 7) / 8;
    // iter 1: h0 -> ha
    k_msg<<<msgBlocks, 256>>>(ei, 0, E);
    k_update<<<nodeBlocks, 256>>>(0, 1, root, bias, N);
    // iter 2: ha -> hb
    k_msg<<<msgBlocks, 256>>>(ei, 1, E);
    k_update<<<nodeBlocks, 256>>>(1, 2, root, bias, N);
    // iter 3: hb -> ha
    k_msg<<<msgBlocks, 256>>>(ei, 2, E);
    k_update<<<nodeBlocks, 256>>>(2, 1, root, bias, N);

    k_zero<<<1, 32>>>(out, out_size);
    k_readout<<<nodeBlocks, 256>>>(Wi0, bi0, Wi1, bi1, Wj0, bj0, Wj1, bj1, out, N);
}

// round 4
// speedup vs baseline: 2.6272x; 1.0810x over previous
#include <cuda_runtime.h>
#include <cuda_fp16.h>
#include <math.h>
#include <stdint.h>

#define MAXE 400000
#define MAXN 50000

// Scratch (device globals: the sanctioned alloc-free workaround)
__device__ __half g_e2h[(size_t)MAXE * 64];    // 51 MB: edge MLP output (fp16)
__device__ __half g_Bt[64 * 1024];             // Wm2 transposed [n][k], fp16
__device__ __half g_Wh[(size_t)MAXE * 1024];   // 819 MB: per-edge 32x32 matrices (fp16)
__device__ float  g_h0[(size_t)MAXN * 32];
__device__ float  g_ha[(size_t)MAXN * 32];
__device__ float  g_hb[(size_t)MAXN * 32];
__device__ float  g_agg[(size_t)MAXN * 32];

// ---------------------------------------------------------------------------
// init: h0 = [x, zeros], agg = 0
// ---------------------------------------------------------------------------
__global__ void k_init(const float* __restrict__ x, int N) {
    int i = blockIdx.x * blockDim.x + threadIdx.x;
    if (i < N * 32) {
        int n = i >> 5, o = i & 31;
        g_h0[i] = (o < 16) ? x[n * 16 + o] : 0.0f;
        g_agg[i] = 0.0f;
    }
}

// ---------------------------------------------------------------------------
// convB: g_Bt[n][k] = fp16(Wm2[k][n])   (64x1024 -> 1024x64)
// ---------------------------------------------------------------------------
__global__ void k_convB(const float* __restrict__ B) {
    int i = blockIdx.x * blockDim.x + threadIdx.x;
    if (i < 64 * 1024) {
        int n = i >> 6, k = i & 63;
        g_Bt[i] = __float2half_rn(B[k * 1024 + n]);
    }
}

// ---------------------------------------------------------------------------
// edge MLP: e2 = relu(relu(ea@Wm0+bm0)@Wm1+bm1)  (fp32 math, fp16 output)
// ---------------------------------------------------------------------------
__global__ __launch_bounds__(128) void k_edge_mlp(
    const float* __restrict__ ea,
    const float* __restrict__ Wm0, const float* __restrict__ bm0,
    const float* __restrict__ Wm1, const float* __restrict__ bm1, int E) {
    __shared__ float sW0[16 * 64];
    __shared__ float sW1[64 * 64];
    __shared__ float sb0[64], sb1[64];
    int tid = threadIdx.x;
    for (int i = tid; i < 16 * 64; i += 128) sW0[i] = Wm0[i];
    for (int i = tid; i < 64 * 64; i += 128) sW1[i] = Wm1[i];
    if (tid < 64) { sb0[tid] = bm0[tid]; sb1[tid] = bm1[tid]; }
    __syncthreads();

    int e = blockIdx.x * 128 + tid;
    if (e >= E) return;

    float a[16];
#pragma unroll
    for (int k4 = 0; k4 < 4; k4++) {
        float4 v = *(const float4*)(ea + (size_t)e * 16 + k4 * 4);
        a[k4 * 4 + 0] = v.x; a[k4 * 4 + 1] = v.y;
        a[k4 * 4 + 2] = v.z; a[k4 * 4 + 3] = v.w;
    }

    float h1[64];
#pragma unroll
    for (int l4 = 0; l4 < 16; l4++) {
        float s0 = sb0[l4 * 4 + 0], s1 = sb0[l4 * 4 + 1];
        float s2 = sb0[l4 * 4 + 2], s3 = sb0[l4 * 4 + 3];
#pragma unroll
        for (int k = 0; k < 16; k++) {
            float4 w = *(const float4*)&sW0[k * 64 + l4 * 4];
            float av = a[k];
            s0 += av * w.x; s1 += av * w.y; s2 += av * w.z; s3 += av * w.w;
        }
        h1[l4 * 4 + 0] = fmaxf(s0, 0.f); h1[l4 * 4 + 1] = fmaxf(s1, 0.f);
        h1[l4 * 4 + 2] = fmaxf(s2, 0.f); h1[l4 * 4 + 3] = fmaxf(s3, 0.f);
    }

    __half* outp = g_e2h + (size_t)e * 64;
#pragma unroll
    for (int j4 = 0; j4 < 16; j4++) {
        float s0 = sb1[j4 * 4 + 0], s1 = sb1[j4 * 4 + 1];
        float s2 = sb1[j4 * 4 + 2], s3 = sb1[j4 * 4 + 3];
#pragma unroll
        for (int l = 0; l < 64; l++) {
            float4 w = *(const float4*)&sW1[l * 64 + j4 * 4];
            float hv = h1[l];
            s0 += hv * w.x; s1 += hv * w.y; s2 += hv * w.z; s3 += hv * w.w;
        }
        __half2 p0 = __floats2half2_rn(fmaxf(s0, 0.f), fmaxf(s1, 0.f));
        __half2 p1 = __floats2half2_rn(fmaxf(s2, 0.f), fmaxf(s3, 0.f));
        uint2 pk;
        pk.x = *(unsigned*)&p0; pk.y = *(unsigned*)&p1;
        *(uint2*)(outp + j4 * 4) = pk;
    }
}

// ---------------------------------------------------------------------------
// W GEMM (fp16 tensor cores): g_Wh[E,1024] = fp16(e2[E,64] @ Wm2[64,1024] + bm2)
// block 128x128, K=64, 8 warps (4M x 2N), mma.m16n8k16.f16.f16.f32
// ---------------------------------------------------------------------------
#define HPITCH 72   // halves per smem row (64 + 8 pad); 144B, 16B-aligned

__global__ __launch_bounds__(256) void k_wgemm(
    const float* __restrict__ bias, int E) {
    __shared__ __half sA[128 * HPITCH];   // [row][k]
    __shared__ __half sB[128 * HPITCH];   // [n][k]  (Bt slice)

    int bm = blockIdx.x * 128;
    int bn = blockIdx.y * 128;
    int tid = threadIdx.x;

    // stage A and Bt tiles (16B vector loads, row-contiguous fp16)
    {
        int r = tid >> 3;          // 0..31
        int x = tid & 7;           // uint4 index within row
#pragma unroll
        for (int i = 0; i < 4; i++) {
            int row = r + i * 32;
            int rr = bm + row; if (rr >= E) rr = E - 1;
            uint4 va = *(const uint4*)(g_e2h + (size_t)rr * 64 + x * 8);
            *(uint4*)((char*)sA + row * 144 + x * 16) = va;
            uint4 vb = *(const uint4*)(g_Bt + (size_t)(bn + row) * 64 + x * 8);
            *(uint4*)((char*)sB + row * 144 + x * 16) = vb;
        }
    }
    __syncthreads();

    int lane = tid & 31;
    int warp = tid >> 5;
    int wm = warp & 3;    // M strip of 32
    int wn = warp >> 2;   // N strip of 64
    int g = lane >> 2;    // groupID
    int c = lane & 3;     // threadID in group

    float acc[2][8][4];
#pragma unroll
    for (int mt = 0; mt < 2; mt++)
#pragma unroll
        for (int nt = 0; nt < 8; nt++)
#pragma unroll
            for (int q = 0; q < 4; q++) acc[mt][nt][q] = 0.f;

#pragma unroll
    for (int kk = 0; kk < 4; kk++) {
        int kb = kk * 16;
        unsigned a_[2][4];
#pragma unroll
        for (int mt = 0; mt < 2; mt++) {
            int r0 = wm * 32 + mt * 16 + g;
            a_[mt][0] = *(const unsigned*)&sA[r0 * HPITCH + kb + 2 * c];
            a_[mt][1] = *(const unsigned*)&sA[(r0 + 8) * HPITCH + kb + 2 * c];
            a_[mt][2] = *(const unsigned*)&sA[r0 * HPITCH + kb + 2 * c + 8];
            a_[mt][3] = *(const unsigned*)&sA[(r0 + 8) * HPITCH + kb + 2 * c + 8];
        }
        unsigned b_[8][2];
#pragma unroll
        for (int nt = 0; nt < 8; nt++) {
            int n0 = wn * 64 + nt * 8 + g;
            b_[nt][0] = *(const unsigned*)&sB[n0 * HPITCH + kb + 2 * c];
            b_[nt][1] = *(const unsigned*)&sB[n0 * HPITCH + kb + 2 * c + 8];
        }
#pragma unroll
        for (int mt = 0; mt < 2; mt++)
#pragma unroll
            for (int nt = 0; nt < 8; nt++) {
                asm volatile(
                    "mma.sync.aligned.m16n8k16.row.col.f32.f16.f16.f32 "
                    "{%0,%1,%2,%3}, {%4,%5,%6,%7}, {%8,%9}, {%0,%1,%2,%3};"
                    : "+f"(acc[mt][nt][0]), "+f"(acc[mt][nt][1]),
                      "+f"(acc[mt][nt][2]), "+f"(acc[mt][nt][3])
                    : "r"(a_[mt][0]), "r"(a_[mt][1]), "r"(a_[mt][2]), "r"(a_[mt][3]),
                      "r"(b_[nt][0]), "r"(b_[nt][1]));
            }
    }

    // epilogue: add bias, write fp16
#pragma unroll
    for (int nt = 0; nt < 8; nt++) {
        int col = bn + wn * 64 + nt * 8 + 2 * c;
        float2 bb = *(const float2*)&bias[col];
#pragma unroll
        for (int mt = 0; mt < 2; mt++) {
            int row0 = bm + wm * 32 + mt * 16 + g;
            if (row0 < E) {
                __half2 v = __floats2half2_rn(acc[mt][nt][0] + bb.x, acc[mt][nt][1] + bb.y);
                *(__half2*)(g_Wh + (size_t)row0 * 1024 + col) = v;
            }
            int row1 = row0 + 8;
            if (row1 < E) {
                __half2 v = __floats2half2_rn(acc[mt][nt][2] + bb.x, acc[mt][nt][3] + bb.y);
                *(__half2*)(g_Wh + (size_t)row1 * 1024 + col) = v;
            }
        }
    }
}

// ---------------------------------------------------------------------------
// message passing: agg[dst] += h[src] @ W_e   (one warp per edge, fp16 W)
// ---------------------------------------------------------------------------
__global__ __launch_bounds__(256) void k_msg(const int* __restrict__ ei, int selIn, int E) {
    int gw = (blockIdx.x * blockDim.x + threadIdx.x) >> 5;
    int lane = threadIdx.x & 31;
    if (gw >= E) return;
    const float* __restrict__ h = (selIn == 0) ? g_h0 : (selIn == 1) ? g_ha : g_hb;

    int2 sd = ((const int2*)ei)[gw];
    int src = sd.x, dst = sd.y;
    float hval = h[(size_t)src * 32 + lane];

    const uint4* __restrict__ W16 = (const uint4*)(g_Wh + (size_t)gw * 1024);
    float acc[8];
#pragma unroll
    for (int j = 0; j < 8; j++) acc[j] = 0.f;

#pragma unroll
    for (int i = 0; i < 4; i++) {
        uint4 w = W16[lane + 32 * i];
        float hs = __shfl_sync(0xffffffffu, hval, (lane >> 2) + 8 * i);
        const __half2* h2 = (const __half2*)&w;
#pragma unroll
        for (int j = 0; j < 4; j++) {
            float2 f = __half22float2(h2[j]);
            acc[2 * j]     += hs * f.x;
            acc[2 * j + 1] += hs * f.y;
        }
    }
#pragma unroll
    for (int m = 4; m <= 16; m <<= 1) {
#pragma unroll
        for (int j = 0; j < 8; j++)
            acc[j] += __shfl_xor_sync(0xffffffffu, acc[j], m);
    }
    int k = lane >> 2;
    float v = acc[0];
    if (k == 1) v = acc[1];
    if (k == 2) v = acc[2];
    if (k == 3) v = acc[3];
    if (k == 4) v = acc[4];
    if (k == 5) v = acc[5];
    if (k == 6) v = acc[6];
    if (k == 7) v = acc[7];
    atomicAdd(&g_agg[(size_t)dst * 32 + ((lane & 3) << 3) + k], v);
}

// ---------------------------------------------------------------------------
// node update: h_out = h_in @ root + bias + agg ; agg = 0   (warp per node)
// ---------------------------------------------------------------------------
__global__ __launch_bounds__(256) void k_update(
    int selIn, int selOut, const float* __restrict__ root,
    const float* __restrict__ bias, int N) {
    __shared__ float sroot[32 * 32];
    __shared__ float sb[32];
    int tid = threadIdx.x;
    for (int i = tid; i < 1024; i += 256) sroot[i] = root[i];
    if (tid < 32) sb[tid] = bias[tid];
    __syncthreads();

    int lane = tid & 31, w = tid >> 5;
    int n = blockIdx.x * 8 + w;
    if (n >= N) return;
    const float* __restrict__ hin = (selIn == 0) ? g_h0 : (selIn == 1) ? g_ha : g_hb;
    float* __restrict__ hout = (selOut == 1) ? g_ha : g_hb;

    float hv = hin[(size_t)n * 32 + lane];
    float acc = sb[lane] + g_agg[(size_t)n * 32 + lane];
    g_agg[(size_t)n * 32 + lane] = 0.0f;
#pragma unroll
    for (int k = 0; k < 32; k++)
        acc += __shfl_sync(0xffffffffu, hv, k) * sroot[k * 32 + lane];
    hout[(size_t)n * 32 + lane] = acc;
}

__global__ void k_zero(float* o, int n) {
    int i = blockIdx.x * blockDim.x + threadIdx.x;
    if (i < n) o[i] = 0.0f;
}

// ---------------------------------------------------------------------------
// readout: out = sum_n sigmoid(relu([h,h0]@Wi0+bi0)@Wi1+bi1) *
//                       (relu(h@Wj0+bj0)@Wj1+bj1)
// ---------------------------------------------------------------------------
__global__ __launch_bounds__(256) void k_readout(
    const float* __restrict__ Wi0, const float* __restrict__ bi0,
    const float* __restrict__ Wi1, const float* __restrict__ bi1,
    const float* __restrict__ Wj0, const float* __restrict__ bj0,
    const float* __restrict__ Wj1, const float* __restrict__ bj1,
    float* __restrict__ out, int N) {
    __shared__ float sW[64 * 128];
    __shared__ float sv1[128];
    __shared__ float sblock;
    int tid = threadIdx.x, lane = tid & 31, w = tid >> 5;
    int n = blockIdx.x * 8 + w;
    bool active = (n < N);

    for (int i = tid; i < 64 * 128; i += 256) sW[i] = Wi0[i];
    for (int i = tid; i < 128; i += 256) sv1[i] = Wi1[i];
    if (tid == 0) sblock = 0.f;
    __syncthreads();

    float za = 0.f, zb = 0.f;
    if (active) {
        za = g_ha[(size_t)n * 32 + lane];   // final h
        zb = g_h0[(size_t)n * 32 + lane];   // h0
    }

    float a0 = bi0[lane], a1 = bi0[lane + 32], a2 = bi0[lane + 64], a3 = bi0[lane + 96];
#pragma unroll
    for (int k = 0; k < 32; k++) {
        float zk = __shfl_sync(0xffffffffu, za, k);
        a0 += zk * sW[k * 128 + lane];
        a1 += zk * sW[k * 128 + lane + 32];
        a2 += zk * sW[k * 128 + lane + 64];
        a3 += zk * sW[k * 128 + lane + 96];
    }
#pragma unroll
    for (int k = 0; k < 32; k++) {
        float zk = __shfl_sync(0xffffffffu, zb, k);
        a0 += zk * sW[(k + 32) * 128 + lane];
        a1 += zk * sW[(k + 32) * 128 + lane + 32];
        a2 += zk * sW[(k + 32) * 128 + lane + 64];
        a3 += zk * sW[(k + 32) * 128 + lane + 96];
    }
    a0 = fmaxf(a0, 0.f); a1 = fmaxf(a1, 0.f); a2 = fmaxf(a2, 0.f); a3 = fmaxf(a3, 0.f);
    float gp = a0 * sv1[lane] + a1 * sv1[lane + 32] + a2 * sv1[lane + 64] + a3 * sv1[lane + 96];
#pragma unroll
    for (int s = 16; s > 0; s >>= 1) gp += __shfl_xor_sync(0xffffffffu, gp, s);
    float gate = 1.0f / (1.0f + expf(-(gp + bi1[0])));

    __syncthreads();   // done reading Wi0
    for (int i = tid; i < 32 * 128; i += 256) sW[i] = Wj0[i];
    for (int i = tid; i < 128; i += 256) sv1[i] = Wj1[i];
    __syncthreads();

    float b0 = bj0[lane], b1 = bj0[lane + 32], b2 = bj0[lane + 64], b3 = bj0[lane + 96];
#pragma unroll
    for (int k = 0; k < 32; k++) {
        float zk = __shfl_sync(0xffffffffu, za, k);
        b0 += zk * sW[k * 128 + lane];
        b1 += zk * sW[k * 128 + lane + 32];
        b2 += zk * sW[k * 128 + lane + 64];
        b3 += zk * sW[k * 128 + lane + 96];
    }
    b0 = fmaxf(b0, 0.f); b1 = fmaxf(b1, 0.f); b2 = fmaxf(b2, 0.f); b3 = fmaxf(b3, 0.f);
    float vp = b0 * sv1[lane] + b1 * sv1[lane + 32] + b2 * sv1[lane + 64] + b3 * sv1[lane + 96];
#pragma unroll
    for (int s = 16; s > 0; s >>= 1) vp += __shfl_xor_sync(0xffffffffu, vp, s);
    float val = vp + bj1[0];

    if (active && lane == 0) atomicAdd(&sblock, gate * val);
    __syncthreads();
    if (tid == 0) atomicAdd(out, sblock);
}

// ---------------------------------------------------------------------------
extern "C" void kernel_launch(void* const* d_in, const int* in_sizes, int n_in,
                              void* d_out, int out_size) {
    const float* x   = (const float*)d_in[0];
    const int*   ei  = (const int*)d_in[1];
    const float* ea  = (const float*)d_in[2];
    const float* Wm0 = (const float*)d_in[3];  const float* bm0 = (const float*)d_in[4];
    const float* Wm1 = (const float*)d_in[5];  const float* bm1 = (const float*)d_in[6];
    const float* Wm2 = (const float*)d_in[7];  const float* bm2 = (const float*)d_in[8];
    const float* root= (const float*)d_in[9];  const float* bias= (const float*)d_in[10];
    const float* Wi0 = (const float*)d_in[11]; const float* bi0 = (const float*)d_in[12];
    const float* Wi1 = (const float*)d_in[13]; const float* bi1 = (const float*)d_in[14];
    const float* Wj0 = (const float*)d_in[15]; const float* bj0 = (const float*)d_in[16];
    const float* Wj1 = (const float*)d_in[17]; const float* bj1 = (const float*)d_in[18];
    int N = in_sizes[0] / 16;
    int E = in_sizes[2] / 16;
    float* out = (float*)d_out;

    k_init<<<(N * 32 + 255) / 256, 256>>>(x, N);
    k_convB<<<(64 * 1024 + 255) / 256, 256>>>(Wm2);
    k_edge_mlp<<<(E + 127) / 128, 128>>>(ea, Wm0, bm0, Wm1, bm1, E);

    dim3 gg((E + 127) / 128, 8);
    k_wgemm<<<gg, 256>>>(bm2, E);

    int msgBlocks = (E + 7) / 8;
    int nodeBlocks = (N + 7) / 8;
    // iter 1: h0 -> ha
    k_msg<<<msgBlocks, 256>>>(ei, 0, E);
    k_update<<<nodeBlocks, 256>>>(0, 1, root, bias, N);
    // iter 2: ha -> hb
    k_msg<<<msgBlocks, 256>>>(ei, 1, E);
    k_update<<<nodeBlocks, 256>>>(1, 2, root, bias, N);
    // iter 3: hb -> ha
    k_msg<<<msgBlocks, 256>>>(ei, 2, E);
    k_update<<<nodeBlocks, 256>>>(2, 1, root, bias, N);

    k_zero<<<1, 32>>>(out, out_size);
    k_readout<<<nodeBlocks, 256>>>(Wi0, bi0, Wi1, bi1, Wj0, bj0, Wj1, bj1, out, N);
}